// round 6
// baseline (speedup 1.0000x reference)
#include <cuda_runtime.h>
#include <cstdint>
#include <cstddef>

#define NTHR 256
#define TB 8
#define NCOMP 256

// smem layout (floats) — NO weight staging; weights are read from global (L1/L2-hot)
// Xst : 131*8   = 1048   input vectors, TRANSPOSED [k][e]
// Hst : 4*128*8 = 4096   activations h1..h4, TRANSPOSED [lvl][k][e]
// Ua  : 128*8   = 1024   backward vector ping, transposed
// Ub  : 128*8   = 1024   backward vector pong, transposed
#define XST_OFF   0
#define HST_OFF   1048
#define UA_OFF    5144
#define UB_OFF    6168
#define SMALL_OFF 7192
#define SMEM_FLOATS (SMALL_OFF + 40)
#define SMEM_BYTES (SMEM_FLOATS * 4)

// backward step: u_out[t] = mask_lvl[t] * sum_k W[t][k] * u_in[k]
// W row read per-thread-contiguous from global (sector-clean), u_in broadcast from smem.
#define BACKSTEP(WG, UIN, UOUT, LVL) do {                                       \
    float a0 = 0.f, a1 = 0.f, a2 = 0.f, a3 = 0.f;                               \
    const float4* wr_ = (const float4*)((WG) + t * 128);                        \
    _Pragma("unroll 8")                                                         \
    for (int k4 = 0; k4 < 32; k4++) {                                           \
        float4 wv = __ldg(wr_ + k4);                                            \
        int k = k4 * 4;                                                         \
        {   float4 uv = *(const float4*)((UIN) + (k + 0) * 8 + bbase);          \
            a0 = fmaf(wv.x, uv.x, a0); a1 = fmaf(wv.x, uv.y, a1);               \
            a2 = fmaf(wv.x, uv.z, a2); a3 = fmaf(wv.x, uv.w, a3); }             \
        {   float4 uv = *(const float4*)((UIN) + (k + 1) * 8 + bbase);          \
            a0 = fmaf(wv.y, uv.x, a0); a1 = fmaf(wv.y, uv.y, a1);               \
            a2 = fmaf(wv.y, uv.z, a2); a3 = fmaf(wv.y, uv.w, a3); }             \
        {   float4 uv = *(const float4*)((UIN) + (k + 2) * 8 + bbase);          \
            a0 = fmaf(wv.z, uv.x, a0); a1 = fmaf(wv.z, uv.y, a1);               \
            a2 = fmaf(wv.z, uv.z, a2); a3 = fmaf(wv.z, uv.w, a3); }             \
        {   float4 uv = *(const float4*)((UIN) + (k + 3) * 8 + bbase);          \
            a0 = fmaf(wv.w, uv.x, a0); a1 = fmaf(wv.w, uv.y, a1);               \
            a2 = fmaf(wv.w, uv.z, a2); a3 = fmaf(wv.w, uv.w, a3); }             \
    }                                                                           \
    float4 hm = *(const float4*)(Hst + (LVL) * 1024 + t * 8 + bbase);           \
    float4 ov;                                                                  \
    ov.x = (hm.x > 0.f) ? a0 : 0.f;                                             \
    ov.y = (hm.y > 0.f) ? a1 : 0.f;                                             \
    ov.z = (hm.z > 0.f) ? a2 : 0.f;                                             \
    ov.w = (hm.w > 0.f) ? a3 : 0.f;                                             \
    *(float4*)((UOUT) + t * 8 + bbase) = ov;                                    \
  } while (0)

__global__ void __launch_bounds__(NTHR)
fused_kernel(const float* __restrict__ centers,
             const float* __restrict__ eps,
             const float* __restrict__ dk,
             const float* __restrict__ Wi,
             const float* __restrict__ Wh,
             const float* __restrict__ bh,
             const float* __restrict__ bf,
             const void* __restrict__ pA2048, const void* __restrict__ pB2048,
             const float* __restrict__ pA128, const float* __restrict__ pB128,
             float* __restrict__ o_res, float* __restrict__ o_fmean,
             float* __restrict__ o_flog, float* __restrict__ o_coeffs,
             float* __restrict__ o_d1c, float* __restrict__ o_d2c,
             float* __restrict__ o_d1o, float* __restrict__ o_d2o,
             float* __restrict__ o_d1f, float* __restrict__ o_d2f)
{
    const int tid = threadIdx.x;

    // ---- fill blocks (odd blockIdx): stream d2f zeros, skip each row's first float4.
    // Small smem footprint lets these co-reside with compute blocks on every SM.
    if (blockIdx.x & 1) {
        int f = blockIdx.x >> 1;
        float4 z = make_float4(0.f, 0.f, 0.f, 0.f);
        float4* base = (float4*)o_d2f + (size_t)f * 8 * 4096;
#pragma unroll
        for (int r = 0; r < 8; r++) {
            float4* row = base + r * 4096;
            for (int i = 1 + tid; i < 4096; i += NTHR)
                __stcs(row + i, z);
        }
        return;
    }

    extern __shared__ float sm[];
    float* Xst = sm + XST_OFF;
    float* Hst = sm + HST_OFF;
    float* Ua  = sm + UA_OFF;
    float* Ub  = sm + UB_OFF;
    float* sS   = sm + SMALL_OFF;
    float* cS   = sS + TB;
    float* xsS  = cS + TB;
    float* valS = xsS + TB;
    int*   idxS = (int*)(valS + TB);

    const int half = tid >> 7;         // warps 0-3: half 0, warps 4-7: half 1
    const int t = tid & 127;           // output neuron
    const int b0 = (blockIdx.x >> 1) * TB;
    const int bbase = half * 4;        // this thread's 4 examples

    // --- resolve ambiguous inputs ---
    const unsigned* ua_ = (const unsigned*)pA2048;
    bool a_idx = true;
#pragma unroll
    for (int i = 0; i < 8; i++) a_idx &= (ua_[i] < 1000u);
    const int*   idxp = (const int*)(a_idx ? pA2048 : pB2048);
    const float* xsp  = (const float*)(a_idx ? pB2048 : pA2048);
    bool a_bi = true;
#pragma unroll
    for (int i = 0; i < 8; i++) a_bi &= (pA128[i] == 0.0f);
    const float* bi = a_bi ? pA128 : pB128;
    const float* Wf = a_bi ? pB128 : pA128;

    // --- phase 0a: per-example scalars ---
    if (tid < TB) {
        int gb = b0 + tid;
        idxS[tid] = idxp[gb];
        cS[tid]   = centers[gb * 4];
        Xst[1 * 8 + tid] = centers[gb * 4 + 1];
        Xst[2 * 8 + tid] = centers[gb * 4 + 2];
        Xst[3 * 8 + tid] = centers[gb * 4 + 3];
        xsS[tid]  = xsp[gb];
    }
    __syncthreads();

    // --- phase 0b: gather feat (transposed into Xst), write fmean/flog ---
#pragma unroll
    for (int ii = 0; ii < 4; ii++) {
        int e2 = tid + NTHR * ii;
        int b = e2 >> 7;
        int k = e2 & 127;
        int gb = b0 + b;
        int id = idxS[b];
        float m  = dk[id * 256 + k];
        float ls = dk[id * 256 + 128 + k];
        float ep = eps[id * 128 + k];
        float ft = fmaf(expf(0.5f * ls), ep, m);
        o_fmean[(size_t)gb * 128 + k] = m;
        o_flog[(size_t)gb * 128 + k]  = ls;
        if (k == 0) {
            float s = 1e-10f + expf(-ft);
            sS[b] = s;
            Xst[b] = cS[b] * s;            // row 0
        } else {
            Xst[(3 + k) * 8 + b] = ft;     // rows 4..130
        }
    }
    __syncthreads();

    // --- L1 forward: h1[t] = relu(sum_k x[k]*Wi[k][t] + bi[t]) ---
    // Weight column reads Wi[k*128+t]: coalesced across warp, L1/L2-hot.
    {
        float bv = bi[t];
        float a0 = bv, a1 = bv, a2 = bv, a3 = bv;
#pragma unroll 8
        for (int k = 0; k < 131; k++) {
            float w = __ldg(Wi + k * 128 + t);
            float4 hv = *(const float4*)(Xst + k * 8 + bbase);
            a0 = fmaf(w, hv.x, a0);
            a1 = fmaf(w, hv.y, a1);
            a2 = fmaf(w, hv.z, a2);
            a3 = fmaf(w, hv.w, a3);
        }
        float4 ov = make_float4(fmaxf(a0, 0.f), fmaxf(a1, 0.f), fmaxf(a2, 0.f), fmaxf(a3, 0.f));
        *(float4*)(Hst + t * 8 + bbase) = ov;
    }
    __syncthreads();

    // --- hidden layers 2..4 ---
#pragma unroll
    for (int l = 0; l < 3; l++) {
        const float* Wg = Wh + l * 16384;
        float bv = bh[l * 128 + t];
        float a0 = bv, a1 = bv, a2 = bv, a3 = bv;
        const float* hin = Hst + l * 1024;
#pragma unroll 8
        for (int k = 0; k < 128; k++) {
            float w = __ldg(Wg + k * 128 + t);
            float4 hv = *(const float4*)(hin + k * 8 + bbase);
            a0 = fmaf(w, hv.x, a0);
            a1 = fmaf(w, hv.y, a1);
            a2 = fmaf(w, hv.z, a2);
            a3 = fmaf(w, hv.w, a3);
        }
        float4 ov = make_float4(fmaxf(a0, 0.f), fmaxf(a1, 0.f), fmaxf(a2, 0.f), fmaxf(a3, 0.f));
        *(float4*)(Hst + (l + 1) * 1024 + t * 8 + bbase) = ov;
        __syncthreads();
    }

    // --- val (warp-per-example) and backward init u4 = Wf .* mask4 ---
    {
        int wrp = tid >> 5, lane = tid & 31;
        float p = 0.f;
#pragma unroll
        for (int j = 0; j < 4; j++) {
            int k = lane + 32 * j;
            p = fmaf(Hst[3 * 1024 + k * 8 + wrp], Wf[k], p);
        }
#pragma unroll
        for (int o = 16; o > 0; o >>= 1) p += __shfl_down_sync(0xffffffffu, p, o);
        if (lane == 0) valS[wrp] = p + bf[0];

        float wf_t = Wf[t];
        float4 hm = *(const float4*)(Hst + 3 * 1024 + t * 8 + bbase);
        float4 ov;
        ov.x = (hm.x > 0.f) ? wf_t : 0.f;
        ov.y = (hm.y > 0.f) ? wf_t : 0.f;
        ov.z = (hm.z > 0.f) ? wf_t : 0.f;
        ov.w = (hm.w > 0.f) ? wf_t : 0.f;
        *(float4*)(Ua + t * 8 + bbase) = ov;
    }
    __syncthreads();

    // --- backward chain (weight rows read per-thread-contiguous from global) ---
    BACKSTEP(Wh + 2 * 16384, Ua, Ub, 2);
    __syncthreads();
    BACKSTEP(Wh + 1 * 16384, Ub, Ua, 1);
    __syncthreads();
    BACKSTEP(Wh + 0 * 16384, Ua, Ub, 0);
    __syncthreads();

    // --- g = Wi @ u1 and all remaining outputs; u1 lives in Ub ---
    {
        float g0 = 0.f, g1 = 0.f, g2 = 0.f, g3 = 0.f;
        const float4* wr = (const float4*)(Wi + t * 128);
#pragma unroll 8
        for (int k4 = 0; k4 < 32; k4++) {
            float4 wv = __ldg(wr + k4);
            int k = k4 * 4;
            {   float4 uv = *(const float4*)(Ub + (k + 0) * 8 + bbase);
                g0 = fmaf(wv.x, uv.x, g0); g1 = fmaf(wv.x, uv.y, g1);
                g2 = fmaf(wv.x, uv.z, g2); g3 = fmaf(wv.x, uv.w, g3); }
            {   float4 uv = *(const float4*)(Ub + (k + 1) * 8 + bbase);
                g0 = fmaf(wv.y, uv.x, g0); g1 = fmaf(wv.y, uv.y, g1);
                g2 = fmaf(wv.y, uv.z, g2); g3 = fmaf(wv.y, uv.w, g3); }
            {   float4 uv = *(const float4*)(Ub + (k + 2) * 8 + bbase);
                g0 = fmaf(wv.z, uv.x, g0); g1 = fmaf(wv.z, uv.y, g1);
                g2 = fmaf(wv.z, uv.z, g2); g3 = fmaf(wv.z, uv.w, g3); }
            {   float4 uv = *(const float4*)(Ub + (k + 3) * 8 + bbase);
                g0 = fmaf(wv.w, uv.x, g0); g1 = fmaf(wv.w, uv.y, g1);
                g2 = fmaf(wv.w, uv.z, g2); g3 = fmaf(wv.w, uv.w, g3); }
        }
        float g[4] = {g0, g1, g2, g3};

        if (t >= 4) {
#pragma unroll
            for (int e = 0; e < 4; e++) {
                int gb = b0 + bbase + e;
                o_d1f[(size_t)gb * 128 + (t - 3)] = g[e];
            }
        } else if (t == 0) {
#pragma unroll
            for (int e = 0; e < 4; e++) {
                int bloc = bbase + e;
                int gb = b0 + bloc;
                float s = sS[bloc], c = cS[bloc], val = valS[bloc];
                float gg = g[e];
                float d1c = gg * s;
                float h00 = gg * c * (s - 1e-10f);   // g0 * c * exp(-ft0)
                o_d1c[gb] = d1c;
                o_d2c[gb] = 0.f;
                o_coeffs[gb] = val;
                o_res[gb] = fmaf(d1c, xsS[bloc] - c, val);
                o_d1f[(size_t)gb * 128] = -h00;
                *(float4*)(o_d2f + (size_t)gb * 16384) = make_float4(h00, 0.f, 0.f, 0.f);
            }
        } else {  // t = 1..3
#pragma unroll
            for (int e = 0; e < 4; e++) {
                int gb = b0 + bbase + e;
                o_d1o[(size_t)gb * 3 + (t - 1)] = g[e];
            }
        }

        // extra Wi rows 128..130 -> d1f[125..127]
        if (t < 3) {
            int r = 128 + t;
            float q0 = 0.f, q1 = 0.f, q2 = 0.f, q3 = 0.f;
            const float4* wr2 = (const float4*)(Wi + r * 128);
#pragma unroll 8
            for (int k4 = 0; k4 < 32; k4++) {
                float4 wv = __ldg(wr2 + k4);
                int k = k4 * 4;
                {   float4 uv = *(const float4*)(Ub + (k + 0) * 8 + bbase);
                    q0 = fmaf(wv.x, uv.x, q0); q1 = fmaf(wv.x, uv.y, q1);
                    q2 = fmaf(wv.x, uv.z, q2); q3 = fmaf(wv.x, uv.w, q3); }
                {   float4 uv = *(const float4*)(Ub + (k + 1) * 8 + bbase);
                    q0 = fmaf(wv.y, uv.x, q0); q1 = fmaf(wv.y, uv.y, q1);
                    q2 = fmaf(wv.y, uv.z, q2); q3 = fmaf(wv.y, uv.w, q3); }
                {   float4 uv = *(const float4*)(Ub + (k + 2) * 8 + bbase);
                    q0 = fmaf(wv.z, uv.x, q0); q1 = fmaf(wv.z, uv.y, q1);
                    q2 = fmaf(wv.z, uv.z, q2); q3 = fmaf(wv.z, uv.w, q3); }
                {   float4 uv = *(const float4*)(Ub + (k + 3) * 8 + bbase);
                    q0 = fmaf(wv.w, uv.x, q0); q1 = fmaf(wv.w, uv.y, q1);
                    q2 = fmaf(wv.w, uv.z, q2); q3 = fmaf(wv.w, uv.w, q3); }
            }
            float ge[4] = {q0, q1, q2, q3};
#pragma unroll
            for (int e = 0; e < 4; e++) {
                int gb = b0 + bbase + e;
                o_d1f[(size_t)gb * 128 + 125 + t] = ge[e];
            }
        }

        // d2o zeros (8 examples x 9 entries)
        if (tid < 72) {
            int b = tid / 9, k9 = tid % 9;
            o_d2o[(size_t)(b0 + b) * 9 + k9] = 0.f;
        }
    }
}

extern "C" void kernel_launch(void* const* d_in, const int* in_sizes, int n_in,
                              void* d_out, int out_size)
{
    (void)out_size;
    const float *centers = 0, *eps = 0, *dk = 0, *Wi = 0, *Wh = 0, *bh = 0, *bf = 0;
    const void* p2048[2] = {0, 0};
    const float* p128[2] = {0, 0};
    int n2 = 0, n1 = 0;
    for (int i = 0; i < n_in; i++) {
        switch (in_sizes[i]) {
            case 8192:   centers = (const float*)d_in[i]; break;  // (2048,4)
            case 128000: eps     = (const float*)d_in[i]; break;  // (1000,128)
            case 256000: dk      = (const float*)d_in[i]; break;  // (1000,256)
            case 16768:  Wi      = (const float*)d_in[i]; break;  // (131,128)
            case 49152:  Wh      = (const float*)d_in[i]; break;  // (3,128,128)
            case 384:    bh      = (const float*)d_in[i]; break;  // (3,128)
            case 1:      bf      = (const float*)d_in[i]; break;  // (1,)
            case 2048:   if (n2 < 2) p2048[n2++] = d_in[i]; break; // indecies / xs
            case 128:    if (n1 < 2) p128[n1++] = (const float*)d_in[i]; break; // bi / Wf
            default: break;
        }
    }
    const int B = 2048;
    float* out = (float*)d_out;
    float* o_res    = out;
    float* o_fmean  = out + B;
    float* o_flog   = o_fmean + (size_t)B * 128;
    float* o_coeffs = o_flog + (size_t)B * 128;
    float* o_d1c    = o_coeffs + B;
    float* o_d2c    = o_d1c + B;
    float* o_d1o    = o_d2c + B;
    float* o_d2o    = o_d1o + (size_t)B * 3;
    float* o_d1f    = o_d2o + (size_t)B * 9;
    float* o_d2f    = o_d1f + (size_t)B * 128;

    // even blocks: compute (256), odd blocks: d2f zero-fill (256); small smem so
    // both kinds co-reside on every SM and stores overlap compute.
    fused_kernel<<<2 * NCOMP, NTHR, SMEM_BYTES>>>(
        centers, eps, dk, Wi, Wh, bh, bf,
        p2048[0], p2048[1], p128[0], p128[1],
        o_res, o_fmean, o_flog, o_coeffs, o_d1c, o_d2c, o_d1o, o_d2o, o_d1f, o_d2f);
}

// round 7
// speedup vs baseline: 1.6685x; 1.6685x over previous
#include <cuda_runtime.h>
#include <cstdint>
#include <cstddef>

#define NTHR 320          // 256 compute threads + 64 store-only threads
#define CTHR 256
#define TB 8
#define NCOMP 256
#define PITCH 132

// smem layout (floats) — identical to the proven R2 kernel
#define WS_OFF   0
#define XS_OFF   17292
#define HS_OFF   18348
#define UA_OFF   22444
#define UB_OFF   23468
#define SMALL_OFF 24492
#define SMEM_FLOATS (SMALL_OFF + 40)
#define SMEM_BYTES (SMEM_FLOATS * 4)

// named barrier for the 256 compute threads only (store warps never join)
#define CBAR() asm volatile("bar.sync 1, 256;" ::: "memory")

__device__ __forceinline__ void stage_w(float* Ws, const float* __restrict__ g, int rows, int tid) {
    for (int i4 = tid; i4 < rows * 32; i4 += CTHR) {
        int r = i4 >> 5, c4 = (i4 & 31) << 2;
        *(float4*)(Ws + r * PITCH + c4) = *(const float4*)(g + r * 128 + c4);
    }
}

#define BACKSTEP(UIN, UOUT, LVL) do {                                           \
    float acc_[4] = {0.f, 0.f, 0.f, 0.f};                                       \
    _Pragma("unroll 8")                                                         \
    for (int k = 0; k < 128; k += 4) {                                          \
        float4 wv = *(const float4*)(Ws + t * PITCH + k);                       \
        _Pragma("unroll")                                                       \
        for (int e = 0; e < 4; e++) {                                           \
            float4 uv = *(const float4*)((UIN) + (bbase + e) * 128 + k);        \
            acc_[e] = fmaf(wv.x, uv.x, acc_[e]);                                \
            acc_[e] = fmaf(wv.y, uv.y, acc_[e]);                                \
            acc_[e] = fmaf(wv.z, uv.z, acc_[e]);                                \
            acc_[e] = fmaf(wv.w, uv.w, acc_[e]);                                \
        }                                                                       \
    }                                                                           \
    _Pragma("unroll")                                                           \
    for (int e = 0; e < 4; e++) {                                               \
        float h = Hs[(LVL) * 1024 + (bbase + e) * 128 + t];                     \
        (UOUT)[(bbase + e) * 128 + t] = (h > 0.f) ? acc_[e] : 0.f;              \
    }                                                                           \
  } while (0)

__global__ void __launch_bounds__(NTHR)
fused_kernel(const float* __restrict__ centers,
             const float* __restrict__ eps,
             const float* __restrict__ dk,
             const float* __restrict__ Wi,
             const float* __restrict__ Wh,
             const float* __restrict__ bh,
             const float* __restrict__ bf,
             const void* __restrict__ pA2048, const void* __restrict__ pB2048,
             const float* __restrict__ pA128, const float* __restrict__ pB128,
             float* __restrict__ o_res, float* __restrict__ o_fmean,
             float* __restrict__ o_flog, float* __restrict__ o_coeffs,
             float* __restrict__ o_d1c, float* __restrict__ o_d2c,
             float* __restrict__ o_d1o, float* __restrict__ o_d2o,
             float* __restrict__ o_d1f, float* __restrict__ o_d2f)
{
    const int tid = threadIdx.x;
    const int b0 = blockIdx.x * TB;

    // ---- store warps (tid 256..319): stream this block's d2f zeros in the
    // background, no barriers. Skip each row's first float4 (written by the
    // compute path as {h00,0,0,0} — disjoint addresses, no race).
    if (tid >= CTHR) {
        int st = tid - CTHR;                 // 0..63
        float4 z = make_float4(0.f, 0.f, 0.f, 0.f);
        float4* base = (float4*)o_d2f + (size_t)b0 * 4096;
#pragma unroll
        for (int r = 0; r < TB; r++) {
            float4* row = base + r * 4096;
            for (int i = 1 + st; i < 4096; i += 64)
                __stcs(row + i, z);
        }
        return;
    }

    extern __shared__ float sm[];
    float* Ws = sm + WS_OFF;
    float* Xs = sm + XS_OFF;
    float* Hs = sm + HS_OFF;
    float* Ua = sm + UA_OFF;
    float* Ub = sm + UB_OFF;
    float* sS   = sm + SMALL_OFF;
    float* cS   = sS + TB;
    float* xsS  = cS + TB;
    float* valS = xsS + TB;
    int*   idxS = (int*)(valS + TB);

    const int half = tid >> 7;
    const int t = tid & 127;
    const int bbase = half * 4;

    // --- resolve ambiguous inputs ---
    const unsigned* ua_ = (const unsigned*)pA2048;
    bool a_idx = true;
#pragma unroll
    for (int i = 0; i < 8; i++) a_idx &= (ua_[i] < 1000u);
    const int*   idxp = (const int*)(a_idx ? pA2048 : pB2048);
    const float* xsp  = (const float*)(a_idx ? pB2048 : pA2048);
    bool a_bi = true;
#pragma unroll
    for (int i = 0; i < 8; i++) a_bi &= (pA128[i] == 0.0f);
    const float* bi = a_bi ? pA128 : pB128;
    const float* Wf = a_bi ? pB128 : pA128;

    // --- phase 0a: per-example scalars ---
    if (tid < TB) {
        int gb = b0 + tid;
        idxS[tid] = idxp[gb];
        cS[tid]   = centers[gb * 4];
        Xs[tid * PITCH + 1] = centers[gb * 4 + 1];
        Xs[tid * PITCH + 2] = centers[gb * 4 + 2];
        Xs[tid * PITCH + 3] = centers[gb * 4 + 3];
        xsS[tid]  = xsp[gb];
    }
    CBAR();

    // --- phase 0b: gather feat, write fmean/flog, build X; stage Wi ---
#pragma unroll
    for (int ii = 0; ii < 4; ii++) {
        int e2 = tid + CTHR * ii;
        int b = e2 >> 7;
        int k = e2 & 127;
        int gb = b0 + b;
        int id = idxS[b];
        float m  = dk[id * 256 + k];
        float ls = dk[id * 256 + 128 + k];
        float ep = eps[id * 128 + k];
        float ft = fmaf(expf(0.5f * ls), ep, m);
        __stcs(o_fmean + (size_t)gb * 128 + k, m);
        __stcs(o_flog  + (size_t)gb * 128 + k, ls);
        if (k == 0) {
            float s = 1e-10f + expf(-ft);
            sS[b] = s;
            Xs[b * PITCH] = cS[b] * s;
        } else {
            Xs[b * PITCH + 3 + k] = ft;
        }
    }
    stage_w(Ws, Wi, 131, tid);
    CBAR();

    // --- L1 forward: h1 = relu(x @ Wi + bi) ---
    {
        float acc[4];
        float bv = bi[t];
#pragma unroll
        for (int e = 0; e < 4; e++) acc[e] = bv;
#pragma unroll 8
        for (int k = 0; k < 128; k += 4) {
            float w0 = Ws[(k    ) * PITCH + t];
            float w1 = Ws[(k + 1) * PITCH + t];
            float w2 = Ws[(k + 2) * PITCH + t];
            float w3 = Ws[(k + 3) * PITCH + t];
#pragma unroll
            for (int e = 0; e < 4; e++) {
                float4 hv = *(const float4*)(Xs + (bbase + e) * PITCH + k);
                acc[e] = fmaf(hv.x, w0, acc[e]);
                acc[e] = fmaf(hv.y, w1, acc[e]);
                acc[e] = fmaf(hv.z, w2, acc[e]);
                acc[e] = fmaf(hv.w, w3, acc[e]);
            }
        }
#pragma unroll
        for (int k = 128; k < 131; k++) {
            float w = Ws[k * PITCH + t];
#pragma unroll
            for (int e = 0; e < 4; e++)
                acc[e] = fmaf(Xs[(bbase + e) * PITCH + k], w, acc[e]);
        }
#pragma unroll
        for (int e = 0; e < 4; e++)
            Hs[(bbase + e) * 128 + t] = fmaxf(acc[e], 0.f);
    }
    CBAR();

    // --- hidden layers 2..4 ---
    for (int l = 0; l < 3; l++) {
        stage_w(Ws, Wh + l * 16384, 128, tid);
        CBAR();
        float acc[4];
        float bv = bh[l * 128 + t];
#pragma unroll
        for (int e = 0; e < 4; e++) acc[e] = bv;
        const float* hin = Hs + l * 1024;
#pragma unroll 8
        for (int k = 0; k < 128; k += 4) {
            float w0 = Ws[(k    ) * PITCH + t];
            float w1 = Ws[(k + 1) * PITCH + t];
            float w2 = Ws[(k + 2) * PITCH + t];
            float w3 = Ws[(k + 3) * PITCH + t];
#pragma unroll
            for (int e = 0; e < 4; e++) {
                float4 hv = *(const float4*)(hin + (bbase + e) * 128 + k);
                acc[e] = fmaf(hv.x, w0, acc[e]);
                acc[e] = fmaf(hv.y, w1, acc[e]);
                acc[e] = fmaf(hv.z, w2, acc[e]);
                acc[e] = fmaf(hv.w, w3, acc[e]);
            }
        }
#pragma unroll
        for (int e = 0; e < 4; e++)
            Hs[(l + 1) * 1024 + (bbase + e) * 128 + t] = fmaxf(acc[e], 0.f);
        CBAR();
    }

    // --- val (warp-per-example) and backward init u4 = Wf .* mask4 ---
    {
        int wrp = tid >> 5, lane = tid & 31;
        const float* h4 = Hs + 3 * 1024 + wrp * 128;
        float4 hv = *(const float4*)(h4 + lane * 4);
        float4 wv = *(const float4*)(Wf + lane * 4);
        float p = hv.x * wv.x + hv.y * wv.y + hv.z * wv.z + hv.w * wv.w;
#pragma unroll
        for (int o = 16; o > 0; o >>= 1) p += __shfl_down_sync(0xffffffffu, p, o);
        if (lane == 0) valS[wrp] = p + bf[0];

        float wf_t = Wf[t];
#pragma unroll
        for (int e = 0; e < 4; e++) {
            float h = Hs[3 * 1024 + (bbase + e) * 128 + t];
            Ua[(bbase + e) * 128 + t] = (h > 0.f) ? wf_t : 0.f;
        }
    }
    CBAR();

    // --- backward: Ws still holds Wh[2] ---
    BACKSTEP(Ua, Ub, 2);
    CBAR();
    stage_w(Ws, Wh + 1 * 16384, 128, tid);
    CBAR();
    BACKSTEP(Ub, Ua, 1);
    CBAR();
    stage_w(Ws, Wh + 0 * 16384, 128, tid);
    CBAR();
    BACKSTEP(Ua, Ub, 0);
    CBAR();

    // --- g = Wi @ u1 from GLOBAL Wi rows (per-thread contiguous, L2-hot) ---
    {
        float g0 = 0.f, g1 = 0.f, g2 = 0.f, g3 = 0.f;
        const float4* wr = (const float4*)(Wi + t * 128);
#pragma unroll 8
        for (int k4 = 0; k4 < 32; k4++) {
            float4 wv = __ldg(wr + k4);
            int k = k4 * 4;
            {   float4 uv = *(const float4*)(Ub + (bbase + 0) * 128 + k);
                g0 = fmaf(wv.x, uv.x, g0); g0 = fmaf(wv.y, uv.y, g0);
                g0 = fmaf(wv.z, uv.z, g0); g0 = fmaf(wv.w, uv.w, g0); }
            {   float4 uv = *(const float4*)(Ub + (bbase + 1) * 128 + k);
                g1 = fmaf(wv.x, uv.x, g1); g1 = fmaf(wv.y, uv.y, g1);
                g1 = fmaf(wv.z, uv.z, g1); g1 = fmaf(wv.w, uv.w, g1); }
            {   float4 uv = *(const float4*)(Ub + (bbase + 2) * 128 + k);
                g2 = fmaf(wv.x, uv.x, g2); g2 = fmaf(wv.y, uv.y, g2);
                g2 = fmaf(wv.z, uv.z, g2); g2 = fmaf(wv.w, uv.w, g2); }
            {   float4 uv = *(const float4*)(Ub + (bbase + 3) * 128 + k);
                g3 = fmaf(wv.x, uv.x, g3); g3 = fmaf(wv.y, uv.y, g3);
                g3 = fmaf(wv.z, uv.z, g3); g3 = fmaf(wv.w, uv.w, g3); }
        }
        float g[4] = {g0, g1, g2, g3};

        if (t >= 4) {
#pragma unroll
            for (int e = 0; e < 4; e++) {
                int gb = b0 + bbase + e;
                o_d1f[(size_t)gb * 128 + (t - 3)] = g[e];
            }
        } else if (t == 0) {
#pragma unroll
            for (int e = 0; e < 4; e++) {
                int bloc = bbase + e;
                int gb = b0 + bloc;
                float s = sS[bloc], c = cS[bloc], val = valS[bloc];
                float gg = g[e];
                float d1c = gg * s;
                float h00 = gg * c * (s - 1e-10f);   // g0 * c * exp(-ft0)
                o_d1c[gb] = d1c;
                o_d2c[gb] = 0.f;
                o_coeffs[gb] = val;
                o_res[gb] = fmaf(d1c, xsS[bloc] - c, val);
                o_d1f[(size_t)gb * 128] = -h00;
                *(float4*)(o_d2f + (size_t)gb * 16384) = make_float4(h00, 0.f, 0.f, 0.f);
            }
        } else {  // t = 1..3
#pragma unroll
            for (int e = 0; e < 4; e++) {
                int gb = b0 + bbase + e;
                o_d1o[(size_t)gb * 3 + (t - 1)] = g[e];
            }
        }

        // extra Wi rows 128..130 -> d1f[125..127]  (global rows)
        if (t < 3) {
            int r = 128 + t;
            float q0 = 0.f, q1 = 0.f, q2 = 0.f, q3 = 0.f;
            const float4* wr2 = (const float4*)(Wi + r * 128);
#pragma unroll 8
            for (int k4 = 0; k4 < 32; k4++) {
                float4 wv = __ldg(wr2 + k4);
                int k = k4 * 4;
                {   float4 uv = *(const float4*)(Ub + (bbase + 0) * 128 + k);
                    q0 = fmaf(wv.x, uv.x, q0); q0 = fmaf(wv.y, uv.y, q0);
                    q0 = fmaf(wv.z, uv.z, q0); q0 = fmaf(wv.w, uv.w, q0); }
                {   float4 uv = *(const float4*)(Ub + (bbase + 1) * 128 + k);
                    q1 = fmaf(wv.x, uv.x, q1); q1 = fmaf(wv.y, uv.y, q1);
                    q1 = fmaf(wv.z, uv.z, q1); q1 = fmaf(wv.w, uv.w, q1); }
                {   float4 uv = *(const float4*)(Ub + (bbase + 2) * 128 + k);
                    q2 = fmaf(wv.x, uv.x, q2); q2 = fmaf(wv.y, uv.y, q2);
                    q2 = fmaf(wv.z, uv.z, q2); q2 = fmaf(wv.w, uv.w, q2); }
                {   float4 uv = *(const float4*)(Ub + (bbase + 3) * 128 + k);
                    q3 = fmaf(wv.x, uv.x, q3); q3 = fmaf(wv.y, uv.y, q3);
                    q3 = fmaf(wv.z, uv.z, q3); q3 = fmaf(wv.w, uv.w, q3); }
            }
            float ge[4] = {q0, q1, q2, q3};
#pragma unroll
            for (int e = 0; e < 4; e++) {
                int gb = b0 + bbase + e;
                o_d1f[(size_t)gb * 128 + 125 + t] = ge[e];
            }
        }

        // d2o zeros (8 examples x 9 entries)
        if (tid < 72) {
            int b = tid / 9, k9 = tid % 9;
            o_d2o[(size_t)(b0 + b) * 9 + k9] = 0.f;
        }
    }
}

extern "C" void kernel_launch(void* const* d_in, const int* in_sizes, int n_in,
                              void* d_out, int out_size)
{
    (void)out_size;
    const float *centers = 0, *eps = 0, *dk = 0, *Wi = 0, *Wh = 0, *bh = 0, *bf = 0;
    const void* p2048[2] = {0, 0};
    const float* p128[2] = {0, 0};
    int n2 = 0, n1 = 0;
    for (int i = 0; i < n_in; i++) {
        switch (in_sizes[i]) {
            case 8192:   centers = (const float*)d_in[i]; break;  // (2048,4)
            case 128000: eps     = (const float*)d_in[i]; break;  // (1000,128)
            case 256000: dk      = (const float*)d_in[i]; break;  // (1000,256)
            case 16768:  Wi      = (const float*)d_in[i]; break;  // (131,128)
            case 49152:  Wh      = (const float*)d_in[i]; break;  // (3,128,128)
            case 384:    bh      = (const float*)d_in[i]; break;  // (3,128)
            case 1:      bf      = (const float*)d_in[i]; break;  // (1,)
            case 2048:   if (n2 < 2) p2048[n2++] = d_in[i]; break; // indecies / xs
            case 128:    if (n1 < 2) p128[n1++] = (const float*)d_in[i]; break; // bi / Wf
            default: break;
        }
    }
    const int B = 2048;
    float* out = (float*)d_out;
    float* o_res    = out;
    float* o_fmean  = out + B;
    float* o_flog   = o_fmean + (size_t)B * 128;
    float* o_coeffs = o_flog + (size_t)B * 128;
    float* o_d1c    = o_coeffs + B;
    float* o_d2c    = o_d1c + B;
    float* o_d1o    = o_d2c + B;
    float* o_d2o    = o_d1o + (size_t)B * 3;
    float* o_d1f    = o_d2o + (size_t)B * 9;
    float* o_d2f    = o_d1f + (size_t)B * 128;

    cudaFuncSetAttribute(fused_kernel, cudaFuncAttributeMaxDynamicSharedMemorySize, SMEM_BYTES);
    fused_kernel<<<NCOMP, NTHR, SMEM_BYTES>>>(
        centers, eps, dk, Wi, Wh, bh, bf,
        p2048[0], p2048[1], p128[0], p128[1],
        o_res, o_fmean, o_flog, o_coeffs, o_d1c, o_d2c, o_d1o, o_d2o, o_d1f, o_d2f);
}